// round 6
// baseline (speedup 1.0000x reference)
#include <cuda_runtime.h>
#include <cuda_bf16.h>
#include <math.h>

#define IMG_H 768
#define IMG_W 768
#define IMG_B 16
#define NPIX  (IMG_B*IMG_H*IMG_W)
#define NPIXD 9437184.0
#define TILE 32
#define BINS 4096
#define NACC 15
#define GRID_X 24
#define GRID_Y 24
#define NBLOCKS (GRID_X*GRID_Y*IMG_B)

__device__ float g_h3i[NPIX], g_h3p[NPIX], g_h3m[NPIX];
__device__ float g_h1i[NPIX], g_h1p[NPIX];

__device__ double       g_acc[NACC];
__device__ unsigned int g_hist[2*BINS];   /* [0,BINS)=yp(body)  [BINS,2BINS)=x_i(body) */
__device__ unsigned int g_done;

#define G3_INIT {0.00147946f,0.00380425f,0.00875347f,0.01802342f,0.03320773f,\
                 0.05475029f,0.08077532f,0.10663899f,0.12597909f,0.13317599f,\
                 0.12597909f,0.10663899f,0.08077532f,0.05475029f,0.03320773f,\
                 0.01802342f,0.00875347f,0.00380425f,0.00147946f}
#define G1_INIT {0.00443305f,0.05400558f,0.24203624f,0.39905030f,0.24203624f,\
                 0.05400558f,0.00443305f}

/* ================= K1: horizontal convolutions, one row per block ============ */
__global__ void __launch_bounds__(192) k_hconv(
    const float* __restrict__ xi, const float* __restrict__ ypred,
    const float* __restrict__ xmid)
{
    const float G3W[19] = G3_INIT;
    const float G1W[7]  = G1_INIT;

    __shared__ float sx[788], sy[788], sz[788];   /* col index = gc + 9 */

    const int tid = threadIdx.x;
    const size_t base = (size_t)blockIdx.y * (IMG_H*IMG_W) + (size_t)blockIdx.x * IMG_W;

    for (int idx = tid; idx < 786; idx += 192) {
        int gc = idx - 9;
        bool in = (unsigned)gc < IMG_W;
        float a = 0.f, b = 0.f, c = 0.f;
        if (in) { a = xi[base+gc]; b = ypred[base+gc]; c = xmid[base+gc]; }
        sx[idx] = a; sy[idx] = b; sz[idx] = c;
    }
    __syncthreads();

    const int c0 = tid * 4;
    float w[24];

    /* --- G3 on xi --- */
#pragma unroll
    for (int j = 0; j < 6; j++) *(float4*)&w[4*j] = *(const float4*)&sx[c0 + 4*j];
    {
        float o0=0.f,o1=0.f,o2=0.f,o3=0.f;
#pragma unroll
        for (int k = 0; k < 19; k++) { float g=G3W[k];
            o0=fmaf(w[k],g,o0); o1=fmaf(w[k+1],g,o1); o2=fmaf(w[k+2],g,o2); o3=fmaf(w[k+3],g,o3); }
        *(float4*)&g_h3i[base+c0] = make_float4(o0,o1,o2,o3);
    }
    /* --- G3 on ypred --- */
#pragma unroll
    for (int j = 0; j < 6; j++) *(float4*)&w[4*j] = *(const float4*)&sy[c0 + 4*j];
    {
        float o0=0.f,o1=0.f,o2=0.f,o3=0.f;
#pragma unroll
        for (int k = 0; k < 19; k++) { float g=G3W[k];
            o0=fmaf(w[k],g,o0); o1=fmaf(w[k+1],g,o1); o2=fmaf(w[k+2],g,o2); o3=fmaf(w[k+3],g,o3); }
        *(float4*)&g_h3p[base+c0] = make_float4(o0,o1,o2,o3);
    }
    /* --- G3 on xmid --- */
#pragma unroll
    for (int j = 0; j < 6; j++) *(float4*)&w[4*j] = *(const float4*)&sz[c0 + 4*j];
    {
        float o0=0.f,o1=0.f,o2=0.f,o3=0.f;
#pragma unroll
        for (int k = 0; k < 19; k++) { float g=G3W[k];
            o0=fmaf(w[k],g,o0); o1=fmaf(w[k+1],g,o1); o2=fmaf(w[k+2],g,o2); o3=fmaf(w[k+3],g,o3); }
        *(float4*)&g_h3m[base+c0] = make_float4(o0,o1,o2,o3);
    }
    /* --- G1 on xi --- */
    {
        float u[10];
#pragma unroll
        for (int j = 0; j < 10; j++) u[j] = sx[c0 + 6 + j];
        float o0=0.f,o1=0.f,o2=0.f,o3=0.f;
#pragma unroll
        for (int k = 0; k < 7; k++) { float g=G1W[k];
            o0=fmaf(u[k],g,o0); o1=fmaf(u[k+1],g,o1); o2=fmaf(u[k+2],g,o2); o3=fmaf(u[k+3],g,o3); }
        *(float4*)&g_h1i[base+c0] = make_float4(o0,o1,o2,o3);
    }
    /* --- G1 on ypred --- */
    {
        float u[10];
#pragma unroll
        for (int j = 0; j < 10; j++) u[j] = sy[c0 + 6 + j];
        float o0=0.f,o1=0.f,o2=0.f,o3=0.f;
#pragma unroll
        for (int k = 0; k < 7; k++) { float g=G1W[k];
            o0=fmaf(u[k],g,o0); o1=fmaf(u[k+1],g,o1); o2=fmaf(u[k+2],g,o2); o3=fmaf(u[k+3],g,o3); }
        *(float4*)&g_h1p[base+c0] = make_float4(o0,o1,o2,o3);
    }
}

/* ================= K2: vertical convs + stencils + reductions ================ */
__global__ void __launch_bounds__(256) k_main(
    const float* __restrict__ ypred, const float* __restrict__ npred,
    const float* __restrict__ xi,    const float* __restrict__ wmap,
    const float* __restrict__ nsyn,  float* __restrict__ out)
{
    const float G3W[19] = G3_INIT;
    const float G1W[7]  = G1_INIT;

    __shared__ float s3i[50*32], s3p[50*32], s3m[50*32];
    __shared__ float s1i[38*32], s1p[38*32];
    __shared__ float sxi[34*34], syp[34*34];
    __shared__ double s_red[NACC];
    __shared__ unsigned int s_islast;
    __shared__ unsigned int pre_yp[257], pre_xi2[257];
    __shared__ float qv[8];
    __shared__ float s_fr[2];

    const int tid = threadIdx.x;
    if (tid < NACC) s_red[tid] = 0.0;

    const int gx0 = blockIdx.x * TILE;
    const int gy0 = blockIdx.y * TILE;
    const size_t base = (size_t)blockIdx.z * (IMG_H*IMG_W);

    /* ---- load smem tiles (coalesced, vertical halo only) ---- */
    for (int idx = tid; idx < 50*32; idx += 256) {
        int r = idx >> 5, c = idx & 31;
        int gy = gy0 + r - 9;
        bool in = (unsigned)gy < IMG_H;
        size_t g = base + (size_t)gy*IMG_W + gx0 + c;
        s3i[idx] = in ? g_h3i[g] : 0.f;
        s3p[idx] = in ? g_h3p[g] : 0.f;
        s3m[idx] = in ? g_h3m[g] : 0.f;
    }
    for (int idx = tid; idx < 38*32; idx += 256) {
        int r = idx >> 5, c = idx & 31;
        int gy = gy0 + r - 3;
        bool in = (unsigned)gy < IMG_H;
        size_t g = base + (size_t)gy*IMG_W + gx0 + c;
        s1i[idx] = in ? g_h1i[g] : 0.f;
        s1p[idx] = in ? g_h1p[g] : 0.f;
    }
    for (int idx = tid; idx < 34*34; idx += 256) {
        int r = idx / 34, c = idx - r*34;
        int gy = gy0 + r - 1, gx = gx0 + c - 1;
        bool in = ((unsigned)gy < IMG_H) && ((unsigned)gx < IMG_W);
        size_t g = base + (size_t)gy*IMG_W + gx;
        sxi[idx] = in ? xi[g]    : 0.f;
        syp[idx] = in ? ypred[g] : 0.f;
    }
    __syncthreads();

    /* ---- vertical convs: thread = (col c, rows r0..r0+3), field-at-a-time ---- */
    const int c  = tid & 31;
    const int r0 = (tid >> 5) << 2;

    float li[4], lp4[4], lm4[4], q1i[4], q1p[4];
    {
        float win[22];
#pragma unroll
        for (int k = 0; k < 22; k++) win[k] = s3i[(r0+k)*32 + c];
        float a0=0.f,a1=0.f,a2=0.f,a3=0.f;
#pragma unroll
        for (int k = 0; k < 19; k++) { float w=G3W[k];
            a0=fmaf(win[k],w,a0); a1=fmaf(win[k+1],w,a1);
            a2=fmaf(win[k+2],w,a2); a3=fmaf(win[k+3],w,a3); }
        li[0]=a0; li[1]=a1; li[2]=a2; li[3]=a3;
#pragma unroll
        for (int k = 0; k < 22; k++) win[k] = s3p[(r0+k)*32 + c];
        a0=a1=a2=a3=0.f;
#pragma unroll
        for (int k = 0; k < 19; k++) { float w=G3W[k];
            a0=fmaf(win[k],w,a0); a1=fmaf(win[k+1],w,a1);
            a2=fmaf(win[k+2],w,a2); a3=fmaf(win[k+3],w,a3); }
        lp4[0]=a0; lp4[1]=a1; lp4[2]=a2; lp4[3]=a3;
#pragma unroll
        for (int k = 0; k < 22; k++) win[k] = s3m[(r0+k)*32 + c];
        a0=a1=a2=a3=0.f;
#pragma unroll
        for (int k = 0; k < 19; k++) { float w=G3W[k];
            a0=fmaf(win[k],w,a0); a1=fmaf(win[k+1],w,a1);
            a2=fmaf(win[k+2],w,a2); a3=fmaf(win[k+3],w,a3); }
        lm4[0]=a0; lm4[1]=a1; lm4[2]=a2; lm4[3]=a3;
    }
    {
        float win[10];
#pragma unroll
        for (int k = 0; k < 10; k++) win[k] = s1i[(r0+k)*32 + c];
        float a0=0.f,a1=0.f,a2=0.f,a3=0.f;
#pragma unroll
        for (int k = 0; k < 7; k++) { float w=G1W[k];
            a0=fmaf(win[k],w,a0); a1=fmaf(win[k+1],w,a1);
            a2=fmaf(win[k+2],w,a2); a3=fmaf(win[k+3],w,a3); }
        q1i[0]=a0; q1i[1]=a1; q1i[2]=a2; q1i[3]=a3;
#pragma unroll
        for (int k = 0; k < 10; k++) win[k] = s1p[(r0+k)*32 + c];
        a0=a1=a2=a3=0.f;
#pragma unroll
        for (int k = 0; k < 7; k++) { float w=G1W[k];
            a0=fmaf(win[k],w,a0); a1=fmaf(win[k+1],w,a1);
            a2=fmaf(win[k+2],w,a2); a3=fmaf(win[k+3],w,a3); }
        q1p[0]=a0; q1p[1]=a1; q1p[2]=a2; q1p[3]=a3;
    }

    /* ---- pointwise + 3x3 stencils + reductions ---- */
    float a_rc=0.f,a_nb=0.f,a_sxi=0.f,a_syp=0.f,a_ex=0.f,a_ey=0.f;
    float a_ntex=0.f,a_tex=0.f,a_nf=0.f,a_hf=0.f,a_ic=0.f;
    float a_nfb=0.f,a_lf=0.f,a_mid=0.f,a_syn=0.f;

#pragma unroll
    for (int j = 0; j < 4; j++) {
        int p = (r0+j+1)*34 + (c+1);
        size_t g = base + (size_t)(gy0 + r0 + j)*IMG_W + (gx0 + c);
        float wv = wmap[g], nv = npred[g], sv = nsyn[g];

        float x00=sxi[p-34-1], x01=sxi[p-34], x02=sxi[p-34+1];
        float x10=sxi[p-1],    x11=sxi[p],    x12=sxi[p+1];
        float x20=sxi[p+34-1], x21=sxi[p+34], x22=sxi[p+34+1];
        float y00=syp[p-34-1], y01=syp[p-34], y02=syp[p-34+1];
        float y10=syp[p-1],    y11=syp[p],    y12=syp[p+1];
        float y20=syp[p+34-1], y21=syp[p+34], y22=syp[p+34+1];

        float gxi_ = (x02-x00) + 2.f*(x12-x10) + (x22-x20);
        float gyi_ = (x20-x00) + 2.f*(x21-x01) + (x22-x02);
        float lapi = x01 + x21 + x10 + x12 - 4.f*x11;
        float gxp_ = (y02-y00) + 2.f*(y12-y10) + (y22-y20);
        float gyp_ = (y20-y00) + 2.f*(y21-y01) + (y22-y02);
        float lapp = y01 + y21 + y10 + y12 - 4.f*y11;
        float xv = x11, pv = y11;

        a_rc += fabsf(pv*wv - xv*wv);
        float gmi = sqrtf(fmaf(gxi_,gxi_, fmaf(gyi_,gyi_, 1e-8f)));
        float gmp = sqrtf(fmaf(gxp_,gxp_, fmaf(gyp_,gyp_, 1e-8f)));
        a_ex += fabsf(gxp_-gxi_);
        a_ey += fabsf(gyp_-gyi_);
        bool body = (xv > 0.15f) && (xv < 0.85f);
        bool flat = gmi < 0.03f;
        bool tex  = (gmi > 0.03f) && (gmi < 0.5f);
        if (body) {
            a_nb += 1.f; a_sxi += xv; a_syp += pv;
            int bp = (int)(pv * (float)BINS); bp = bp < 0 ? 0 : (bp > BINS-1 ? BINS-1 : bp);
            int bx = (int)(xv * (float)BINS); bx = bx < 0 ? 0 : (bx > BINS-1 ? BINS-1 : bx);
            atomicAdd(&g_hist[bp], 1u);
            atomicAdd(&g_hist[BINS + bx], 1u);
        }
        if (tex) { a_ntex += 1.f; a_tex += fabsf(gmp - gmi); }
        if (flat) {
            a_nf += 1.f;
            a_hf += fabsf(fabsf(lapp) - 0.3f*fabsf(lapi));
            a_ic += fmaxf(gmp - 2.0f*gmi, 0.f);
            if (body) {
                a_nfb += 1.f;
                a_lf  += fabsf((lp4[j]-lm4[j]) - 0.3f*(li[j]-lm4[j]));
                float mi = q1i[j]-li[j], mp = q1p[j]-lp4[j];
                a_mid += fabsf(fabsf(mp) - 0.3f*fabsf(mi));
                a_syn += fabsf(nv - sv);
            }
        }
    }

    /* block reduction */
    {
        float vals[NACC] = {a_rc,a_nb,a_sxi,a_syp,a_ex,a_ey,a_ntex,a_tex,
                            a_nf,a_hf,a_ic,a_nfb,a_lf,a_mid,a_syn};
#pragma unroll
        for (int i = 0; i < NACC; i++) {
            float v = vals[i];
#pragma unroll
            for (int off = 16; off; off >>= 1) v += __shfl_down_sync(0xffffffffu, v, off);
            if ((tid & 31) == 0) atomicAdd(&s_red[i], (double)v);
        }
    }
    __syncthreads();
    if (tid < NACC) atomicAdd(&g_acc[tid], s_red[tid]);

    /* ---- last-block finalize ---- */
    __threadfence();
    if (tid == 0) {
        unsigned int prev = atomicAdd(&g_done, 1u);
        s_islast = (prev == NBLOCKS-1) ? 1u : 0u;
    }
    __syncthreads();
    if (!s_islast) return;
    __threadfence();

    {
        const int t = tid;
        unsigned int syph = 0, sxih = 0;
#pragma unroll
        for (int i = 0; i < 16; i++) {
            syph += g_hist[t*16 + i];
            sxih += g_hist[BINS + t*16 + i];
        }
        pre_yp[t] = syph; pre_xi2[t] = sxih;
        if (t < 8) qv[t] = 0.f;
        __syncthreads();
        if (t == 0) {
            unsigned int run = 0;
            for (int i = 0; i < 256; i++) { unsigned int x = pre_yp[i]; pre_yp[i] = run; run += x; }
            pre_yp[256] = run;
            run = 0;
            for (int i = 0; i < 256; i++) { unsigned int x = pre_xi2[i]; pre_xi2[i] = run; run += x; }
            pre_xi2[256] = run;
        }
        __syncthreads();

        long long n = (long long)pre_xi2[256];
        long long ranks[4] = {0,0,0,0};
        float fr25 = 0.f, fr75 = 0.f;
        if (n > 0) {
            float pos25 = 0.25f * (float)(n-1);
            float pos75 = 0.75f * (float)(n-1);
            fr25 = pos25 - floorf(pos25);
            fr75 = pos75 - floorf(pos75);
            ranks[0] = (long long)floorf(pos25);
            ranks[1] = (long long)ceilf(pos25);
            ranks[2] = (long long)floorf(pos75);
            ranks[3] = (long long)ceilf(pos75);
        }
        if (t == 0) { s_fr[0] = fr25; s_fr[1] = fr75; }
        {
            long long cum = (long long)pre_yp[t];
            for (int i = 0; i < 16; i++) {
                unsigned int cnt = g_hist[t*16 + i];
#pragma unroll
                for (int j = 0; j < 4; j++) {
                    if (ranks[j] >= cum && ranks[j] < cum + (long long)cnt)
                        qv[j] = ((float)(t*16+i) + ((float)(ranks[j]-cum) + 0.5f)/(float)cnt) * (1.0f/(float)BINS);
                }
                cum += cnt;
            }
        }
        {
            long long cum = (long long)pre_xi2[t];
            for (int i = 0; i < 16; i++) {
                unsigned int cnt = g_hist[BINS + t*16 + i];
#pragma unroll
                for (int j = 0; j < 4; j++) {
                    if (ranks[j] >= cum && ranks[j] < cum + (long long)cnt)
                        qv[4+j] = ((float)(t*16+i) + ((float)(ranks[j]-cum) + 0.5f)/(float)cnt) * (1.0f/(float)BINS);
                }
                cum += cnt;
            }
        }
        __syncthreads();

        if (t == 0) {
            double nb      = g_acc[1];
            double rc      = g_acc[0] / NPIXD;
            double edge    = (g_acc[4] + g_acc[5]) / NPIXD;
            double mean_in = g_acc[2] / fmax(nb, 1.0);
            double mean_pr = g_acc[3] / fmax(nb, 1.0);
            float f25 = s_fr[0], f75 = s_fr[1];
            float q25p = qv[0]*(1.f-f25) + qv[1]*f25;
            float q75p = qv[2]*(1.f-f75) + qv[3]*f75;
            float q25i = qv[4]*(1.f-f25) + qv[5]*f25;
            float q75i = qv[6]*(1.f-f75) + qv[7]*f75;
            double dm   = mean_pr - mean_in;
            double dq25 = (double)q25p - (double)q25i;
            double dq75 = (double)q75p - (double)q75i;
            double hu   = dm*dm + 0.5*(dq25*dq25 + dq75*dq75);
            double loss_hu  = (nb > 4096.0) ? hu : 0.0;
            double ntex = g_acc[6];
            double loss_tex = (ntex > 100.0) ? g_acc[7]/fmax(ntex,1.0) : 0.0;
            double nf   = g_acc[8];
            double loss_hf  = (nf > 100.0) ? g_acc[9]/fmax(nf,1.0)  : 0.0;
            double loss_ic  = (nf > 100.0) ? g_acc[10]/fmax(nf,1.0) : 0.0;
            double nfb  = g_acc[11];
            double loss_lf  = (nfb > 100.0) ? g_acc[12]/fmax(nfb,1.0) : 0.0;
            double loss_mid = (nfb > 100.0) ? g_acc[13]/fmax(nfb,1.0) : 0.0;
            double loss_syn = (nfb > 100.0) ? g_acc[14]/fmax(nfb,1.0) : 0.0;
            double total = 2.0*rc + 1.5*loss_hu + 1.0*edge + 0.8*loss_tex
                         + 1.5*loss_hf + 0.8*loss_mid + 0.6*loss_lf
                         + 1.0*loss_syn + 0.8*loss_ic;
            out[0] = (float)total;
        }
        __syncthreads();

        /* self-clean for next graph replay */
        for (int i = t; i < 2*BINS; i += 256) g_hist[i] = 0u;
        if (t < NACC) g_acc[t] = 0.0;
        if (t == 0)  g_done = 0u;
    }
}

extern "C" void kernel_launch(void* const* d_in, const int* in_sizes, int n_in,
                              void* d_out, int out_size)
{
    (void)in_sizes; (void)n_in; (void)out_size;
    const float* ypred = (const float*)d_in[0];
    const float* npred = (const float*)d_in[1];
    const float* xi    = (const float*)d_in[2];
    /* d_in[3] = x_ip1 unused by the reference */
    const float* xmid  = (const float*)d_in[4];
    const float* wmap  = (const float*)d_in[5];
    const float* nsyn  = (const float*)d_in[6];

    dim3 g1(IMG_H, IMG_B);
    k_hconv<<<g1, 192>>>(xi, ypred, xmid);

    dim3 g2(GRID_X, GRID_Y, IMG_B);
    k_main<<<g2, 256>>>(ypred, npred, xi, wmap, nsyn, (float*)d_out);
}

// round 7
// speedup vs baseline: 1.4567x; 1.4567x over previous
#include <cuda_runtime.h>
#include <cuda_bf16.h>
#include <math.h>

#define IMG_H 768
#define IMG_W 768
#define IMG_B 16
#define NPIXD 9437184.0
#define TILE 32
#define RAW_W 50            /* raw tiles: rows/cols gy0-9..gy0+40 */
#define H3W 34              /* padded row stride for conv intermediates */
#define BINS 4096
#define NACC 15
#define GRID_X 24
#define GRID_Y 24
#define NBLOCKS (GRID_X*GRID_Y*IMG_B)

/* dynamic smem float offsets */
#define O_XI   0            /* 2500 */
#define O_YP   2500
#define O_XM   5000
#define O_H3I  7500         /* 50*34 = 1700 */
#define O_H3P  9200
#define O_H3M  10900
#define O_H1I  12600        /* 38*34 = 1292 */
#define O_H1P  13892
#define SMEM_FLOATS 15184   /* 60736 bytes */

typedef unsigned long long u64;

__device__ double       g_acc[NACC];
__device__ unsigned int g_hist[2*BINS];   /* [0,BINS)=yp(body)  [BINS,2BINS)=x_i(body) */
__device__ unsigned int g_done;

#define G3_INIT {0.00147946f,0.00380425f,0.00875347f,0.01802342f,0.03320773f,\
                 0.05475029f,0.08077532f,0.10663899f,0.12597909f,0.13317599f,\
                 0.12597909f,0.10663899f,0.08077532f,0.05475029f,0.03320773f,\
                 0.01802342f,0.00875347f,0.00380425f,0.00147946f}
#define G1_INIT {0.00443305f,0.05400558f,0.24203624f,0.39905030f,0.24203624f,\
                 0.05400558f,0.00443305f}

__device__ __forceinline__ u64 pack2(float a, float b) {
    u64 r; asm("mov.b64 %0,{%1,%2};" : "=l"(r) : "f"(a), "f"(b)); return r;
}
__device__ __forceinline__ void unpack2(u64 v, float &a, float &b) {
    asm("mov.b64 {%0,%1},%2;" : "=f"(a), "=f"(b) : "l"(v));
}
__device__ __forceinline__ void ffma2(u64 &acc, u64 x, u64 w) {
    asm("fma.rn.f32x2 %0,%1,%2,%0;" : "+l"(acc) : "l"(x), "l"(w));
}

__global__ void __launch_bounds__(256, 3) k_main(
    const float* __restrict__ ypred, const float* __restrict__ npred,
    const float* __restrict__ xi,    const float* __restrict__ xmid,
    const float* __restrict__ wmap,  const float* __restrict__ nsyn,
    float* __restrict__ out)
{
    const float G3W[19] = G3_INIT;
    const float G1W[7]  = G1_INIT;

    extern __shared__ float sm[];
    float* s_xi = sm + O_XI;
    float* s_yp = sm + O_YP;
    float* s_xm = sm + O_XM;
    float* h3i  = sm + O_H3I;
    float* h3p  = sm + O_H3P;
    float* h3m  = sm + O_H3M;
    float* h1i  = sm + O_H1I;
    float* h1p  = sm + O_H1P;

    __shared__ u64 w3tab[19];
    __shared__ u64 w1tab[7];
    __shared__ double s_red[NACC];
    __shared__ unsigned int s_islast;
    __shared__ float s_fr[2];
    __shared__ float qv[8];

    const int tid = threadIdx.x;
    if (tid < NACC) s_red[tid] = 0.0;
    if (tid == 0) {
#pragma unroll
        for (int k = 0; k < 19; k++) w3tab[k] = pack2(G3W[k], G3W[k]);
#pragma unroll
        for (int k = 0; k < 7; k++)  w1tab[k] = pack2(G1W[k], G1W[k]);
    }

    const int gx0 = blockIdx.x * TILE;
    const int gy0 = blockIdx.y * TILE;
    const size_t base = (size_t)blockIdx.z * (IMG_H*IMG_W);

    /* ---- phase 1: load zero-padded raw tiles (scalar, coalesced) ---- */
    for (int idx = tid; idx < RAW_W*RAW_W; idx += 256) {
        int r = idx / RAW_W, c = idx - r*RAW_W;
        int gy = gy0 + r - 9, gx = gx0 + c - 9;
        bool inb = ((unsigned)gy < IMG_H) && ((unsigned)gx < IMG_W);
        size_t g = base + (size_t)gy*IMG_W + gx;
        s_xi[idx] = inb ? xi[g]    : 0.f;
        s_yp[idx] = inb ? ypred[g] : 0.f;
        s_xm[idx] = inb ? xmid[g]  : 0.f;
    }
    __syncthreads();

    /* ---- phase 2: horizontal convs, packed f32x2, 8 outputs/thread ---- */
    {
        const int row = tid & 63, seg = tid >> 6;
        const int c0 = seg * 8;
        if (row < 50) {
            const int bi = row*RAW_W + c0;     /* taps for out c0..c0+7 = raw [c0..c0+25] */
            const int bo = row*H3W + c0;
            const float* srcs[3] = { s_xi, s_yp, s_xm };
            float* dsts[3] = { h3i, h3p, h3m };
#pragma unroll
            for (int f = 0; f < 3; f++) {
                const float* s = srcs[f];
                u64 e[13]; float w[26];
#pragma unroll
                for (int j = 0; j < 13; j++) e[j] = *(const u64*)&s[bi + 2*j];
#pragma unroll
                for (int j = 0; j < 13; j++) unpack2(e[j], w[2*j], w[2*j+1]);
                u64 p[25];
#pragma unroll
                for (int j = 0; j < 13; j++) p[2*j] = e[j];
#pragma unroll
                for (int j = 0; j < 12; j++) p[2*j+1] = pack2(w[2*j+1], w[2*j+2]);
                u64 a0=0ull, a1=0ull, a2=0ull, a3=0ull;
#pragma unroll
                for (int k = 0; k < 19; k++) {
                    u64 wk = w3tab[k];
                    ffma2(a0, p[k],   wk);
                    ffma2(a1, p[k+2], wk);
                    ffma2(a2, p[k+4], wk);
                    ffma2(a3, p[k+6], wk);
                }
                float* d = dsts[f];
                *(u64*)&d[bo]   = a0;
                *(u64*)&d[bo+2] = a1;
                *(u64*)&d[bo+4] = a2;
                *(u64*)&d[bo+6] = a3;
            }
        }
        if (row < 38) {
            /* out col c0+i taps raw cols c0+i-3..c0+i+3 -> raw idx c0+6+i..c0+12+i */
            const int bi = (row+6)*RAW_W + c0 + 6;
            const int bo = row*H3W + c0;
            const float* srcs[2] = { s_xi, s_yp };
            float* dsts[2] = { h1i, h1p };
#pragma unroll
            for (int f = 0; f < 2; f++) {
                const float* s = srcs[f];
                u64 e[7]; float u[14];
#pragma unroll
                for (int j = 0; j < 7; j++) e[j] = *(const u64*)&s[bi + 2*j];
#pragma unroll
                for (int j = 0; j < 7; j++) unpack2(e[j], u[2*j], u[2*j+1]);
                u64 p[13];
#pragma unroll
                for (int j = 0; j < 7; j++) p[2*j] = e[j];
#pragma unroll
                for (int j = 0; j < 6; j++) p[2*j+1] = pack2(u[2*j+1], u[2*j+2]);
                u64 a0=0ull, a1=0ull, a2=0ull, a3=0ull;
#pragma unroll
                for (int k = 0; k < 7; k++) {
                    u64 wk = w1tab[k];
                    ffma2(a0, p[k],   wk);
                    ffma2(a1, p[k+2], wk);
                    ffma2(a2, p[k+4], wk);
                    ffma2(a3, p[k+6], wk);
                }
                float* d = dsts[f];
                *(u64*)&d[bo]   = a0;
                *(u64*)&d[bo+2] = a1;
                *(u64*)&d[bo+4] = a2;
                *(u64*)&d[bo+6] = a3;
            }
        }
    }
    __syncthreads();

    /* ---- phase 3: vertical convs, 2 cols x 2 rows per thread, natural packing ---- */
    const int cp = tid & 15;          /* col pair 0..15 */
    const int rg = tid >> 4;          /* row pair 0..15 */
    const int cc = cp * 2;
    const int r0 = rg * 2;

    u64 v3[3][2];  /* [field][row], each = {col cc, col cc+1} */
    u64 v1[2][2];
    {
        const float* hs[3] = { h3i, h3p, h3m };
#pragma unroll
        for (int f = 0; f < 3; f++) {
            const float* h = hs[f];
            u64 a0=0ull, a1=0ull;
#pragma unroll
            for (int k = 0; k < 20; k++) {
                u64 v = *(const u64*)&h[(r0+k)*H3W + cc];
                if (k < 19) ffma2(a0, v, w3tab[k]);
                if (k > 0)  ffma2(a1, v, w3tab[k-1]);
            }
            v3[f][0]=a0; v3[f][1]=a1;
        }
        const float* hs1[2] = { h1i, h1p };
#pragma unroll
        for (int f = 0; f < 2; f++) {
            const float* h = hs1[f];
            u64 a0=0ull, a1=0ull;
#pragma unroll
            for (int k = 0; k < 8; k++) {
                u64 v = *(const u64*)&h[(r0+k)*H3W + cc];
                if (k < 7) ffma2(a0, v, w1tab[k]);
                if (k > 0) ffma2(a1, v, w1tab[k-1]);
            }
            v1[f][0]=a0; v1[f][1]=a1;
        }
    }
    float li[2][2], lp[2][2], lm[2][2], qi[2][2], qp[2][2];
#pragma unroll
    for (int j = 0; j < 2; j++) {
        unpack2(v3[0][j], li[j][0], li[j][1]);
        unpack2(v3[1][j], lp[j][0], lp[j][1]);
        unpack2(v3[2][j], lm[j][0], lm[j][1]);
        unpack2(v1[0][j], qi[j][0], qi[j][1]);
        unpack2(v1[1][j], qp[j][0], qp[j][1]);
    }

    /* ---- phase 4: pointwise + 3x3 stencils (4x4 shared window) ---- */
    float X[4][4], Y[4][4];
#pragma unroll
    for (int dr = 0; dr < 4; dr++)
#pragma unroll
        for (int dc = 0; dc < 4; dc++) {
            int p = (r0+dr+8)*RAW_W + (cc+dc+8);
            X[dr][dc] = s_xi[p];
            Y[dr][dc] = s_yp[p];
        }

    float a_rc=0.f,a_nb=0.f,a_sxi=0.f,a_syp=0.f,a_ex=0.f,a_ey=0.f;
    float a_ntex=0.f,a_tex=0.f,a_nf=0.f,a_hf=0.f,a_ic=0.f;
    float a_nfb=0.f,a_lf=0.f,a_mid=0.f,a_syn=0.f;

#pragma unroll
    for (int j = 0; j < 2; j++) {
        size_t g = base + (size_t)(gy0 + r0 + j)*IMG_W + (gx0 + cc);
        float2 wv2 = *(const float2*)&wmap[g];
        float2 nv2 = *(const float2*)&npred[g];
        float2 sv2 = *(const float2*)&nsyn[g];
#pragma unroll
        for (int i = 0; i < 2; i++) {
            float wv = i ? wv2.y : wv2.x;
            float nv = i ? nv2.y : nv2.x;
            float sv = i ? sv2.y : sv2.x;

            float gxi_ = (X[j][i+2]-X[j][i]) + 2.f*(X[j+1][i+2]-X[j+1][i]) + (X[j+2][i+2]-X[j+2][i]);
            float gyi_ = (X[j+2][i]-X[j][i]) + 2.f*(X[j+2][i+1]-X[j][i+1]) + (X[j+2][i+2]-X[j][i+2]);
            float lapi = X[j][i+1] + X[j+2][i+1] + X[j+1][i] + X[j+1][i+2] - 4.f*X[j+1][i+1];
            float gxp_ = (Y[j][i+2]-Y[j][i]) + 2.f*(Y[j+1][i+2]-Y[j+1][i]) + (Y[j+2][i+2]-Y[j+2][i]);
            float gyp_ = (Y[j+2][i]-Y[j][i]) + 2.f*(Y[j+2][i+1]-Y[j][i+1]) + (Y[j+2][i+2]-Y[j][i+2]);
            float lapp = Y[j][i+1] + Y[j+2][i+1] + Y[j+1][i] + Y[j+1][i+2] - 4.f*Y[j+1][i+1];
            float xv = X[j+1][i+1], pv = Y[j+1][i+1];

            a_rc += fabsf(pv*wv - xv*wv);
            float gmi = sqrtf(fmaf(gxi_,gxi_, fmaf(gyi_,gyi_, 1e-8f)));
            float gmp = sqrtf(fmaf(gxp_,gxp_, fmaf(gyp_,gyp_, 1e-8f)));
            a_ex += fabsf(gxp_-gxi_);
            a_ey += fabsf(gyp_-gyi_);
            bool body = (xv > 0.15f) && (xv < 0.85f);
            bool flat = gmi < 0.03f;
            bool tex  = (gmi > 0.03f) && (gmi < 0.5f);
            if (body) {
                a_nb += 1.f; a_sxi += xv; a_syp += pv;
                int bp = (int)(pv * (float)BINS); bp = bp < 0 ? 0 : (bp > BINS-1 ? BINS-1 : bp);
                int bx = (int)(xv * (float)BINS); bx = bx < 0 ? 0 : (bx > BINS-1 ? BINS-1 : bx);
                atomicAdd(&g_hist[bp], 1u);
                atomicAdd(&g_hist[BINS + bx], 1u);
            }
            if (tex) { a_ntex += 1.f; a_tex += fabsf(gmp - gmi); }
            if (flat) {
                a_nf += 1.f;
                a_hf += fabsf(fabsf(lapp) - 0.3f*fabsf(lapi));
                a_ic += fmaxf(gmp - 2.0f*gmi, 0.f);
                if (body) {
                    a_nfb += 1.f;
                    a_lf  += fabsf((lp[j][i]-lm[j][i]) - 0.3f*(li[j][i]-lm[j][i]));
                    float mi = qi[j][i]-li[j][i], mp = qp[j][i]-lp[j][i];
                    a_mid += fabsf(fabsf(mp) - 0.3f*fabsf(mi));
                    a_syn += fabsf(nv - sv);
                }
            }
        }
    }

    /* block reduction: warp shuffle -> smem double -> global double */
    {
        float vals[NACC] = {a_rc,a_nb,a_sxi,a_syp,a_ex,a_ey,a_ntex,a_tex,
                            a_nf,a_hf,a_ic,a_nfb,a_lf,a_mid,a_syn};
#pragma unroll
        for (int i = 0; i < NACC; i++) {
            float v = vals[i];
#pragma unroll
            for (int off = 16; off; off >>= 1) v += __shfl_down_sync(0xffffffffu, v, off);
            if ((tid & 31) == 0) atomicAdd(&s_red[i], (double)v);
        }
    }
    __syncthreads();
    if (tid < NACC) atomicAdd(&g_acc[tid], s_red[tid]);

    /* ---- last-block finalize ---- */
    __threadfence();
    if (tid == 0) {
        unsigned int prev = atomicAdd(&g_done, 1u);
        s_islast = (prev == NBLOCKS-1) ? 1u : 0u;
    }
    __syncthreads();
    if (!s_islast) return;
    __threadfence();

    {
        /* overlay scan arrays on dynamic smem (safe: only this block alive here) */
        unsigned int* pre_yp  = (unsigned int*)sm;
        unsigned int* pre_xi2 = pre_yp + 257;
        const int t = tid;

        unsigned int syph = 0, sxih = 0;
#pragma unroll
        for (int i = 0; i < 16; i++) {
            syph += g_hist[t*16 + i];
            sxih += g_hist[BINS + t*16 + i];
        }
        __syncthreads();
        pre_yp[t] = syph; pre_xi2[t] = sxih;
        if (t < 8) qv[t] = 0.f;
        __syncthreads();
        if (t == 0) {
            unsigned int run = 0;
            for (int i = 0; i < 256; i++) { unsigned int x = pre_yp[i]; pre_yp[i] = run; run += x; }
            pre_yp[256] = run;
            run = 0;
            for (int i = 0; i < 256; i++) { unsigned int x = pre_xi2[i]; pre_xi2[i] = run; run += x; }
            pre_xi2[256] = run;
        }
        __syncthreads();

        long long n = (long long)pre_xi2[256];
        long long ranks[4] = {0,0,0,0};
        float fr25 = 0.f, fr75 = 0.f;
        if (n > 0) {
            float pos25 = 0.25f * (float)(n-1);
            float pos75 = 0.75f * (float)(n-1);
            fr25 = pos25 - floorf(pos25);
            fr75 = pos75 - floorf(pos75);
            ranks[0] = (long long)floorf(pos25);
            ranks[1] = (long long)ceilf(pos25);
            ranks[2] = (long long)floorf(pos75);
            ranks[3] = (long long)ceilf(pos75);
        }
        if (t == 0) { s_fr[0] = fr25; s_fr[1] = fr75; }
        {
            long long cum = (long long)pre_yp[t];
            for (int i = 0; i < 16; i++) {
                unsigned int cnt = g_hist[t*16 + i];
#pragma unroll
                for (int j = 0; j < 4; j++) {
                    if (ranks[j] >= cum && ranks[j] < cum + (long long)cnt)
                        qv[j] = ((float)(t*16+i) + ((float)(ranks[j]-cum) + 0.5f)/(float)cnt) * (1.0f/(float)BINS);
                }
                cum += cnt;
            }
        }
        {
            long long cum = (long long)pre_xi2[t];
            for (int i = 0; i < 16; i++) {
                unsigned int cnt = g_hist[BINS + t*16 + i];
#pragma unroll
                for (int j = 0; j < 4; j++) {
                    if (ranks[j] >= cum && ranks[j] < cum + (long long)cnt)
                        qv[4+j] = ((float)(t*16+i) + ((float)(ranks[j]-cum) + 0.5f)/(float)cnt) * (1.0f/(float)BINS);
                }
                cum += cnt;
            }
        }
        __syncthreads();

        if (t == 0) {
            double nb      = g_acc[1];
            double rc      = g_acc[0] / NPIXD;
            double edge    = (g_acc[4] + g_acc[5]) / NPIXD;
            double mean_in = g_acc[2] / fmax(nb, 1.0);
            double mean_pr = g_acc[3] / fmax(nb, 1.0);
            float f25 = s_fr[0], f75 = s_fr[1];
            float q25p = qv[0]*(1.f-f25) + qv[1]*f25;
            float q75p = qv[2]*(1.f-f75) + qv[3]*f75;
            float q25i = qv[4]*(1.f-f25) + qv[5]*f25;
            float q75i = qv[6]*(1.f-f75) + qv[7]*f75;
            double dm   = mean_pr - mean_in;
            double dq25 = (double)q25p - (double)q25i;
            double dq75 = (double)q75p - (double)q75i;
            double hu   = dm*dm + 0.5*(dq25*dq25 + dq75*dq75);
            double loss_hu  = (nb > 4096.0) ? hu : 0.0;
            double ntex = g_acc[6];
            double loss_tex = (ntex > 100.0) ? g_acc[7]/fmax(ntex,1.0) : 0.0;
            double nf   = g_acc[8];
            double loss_hf  = (nf > 100.0) ? g_acc[9]/fmax(nf,1.0)  : 0.0;
            double loss_ic  = (nf > 100.0) ? g_acc[10]/fmax(nf,1.0) : 0.0;
            double nfb  = g_acc[11];
            double loss_lf  = (nfb > 100.0) ? g_acc[12]/fmax(nfb,1.0) : 0.0;
            double loss_mid = (nfb > 100.0) ? g_acc[13]/fmax(nfb,1.0) : 0.0;
            double loss_syn = (nfb > 100.0) ? g_acc[14]/fmax(nfb,1.0) : 0.0;
            double total = 2.0*rc + 1.5*loss_hu + 1.0*edge + 0.8*loss_tex
                         + 1.5*loss_hf + 0.8*loss_mid + 0.6*loss_lf
                         + 1.0*loss_syn + 0.8*loss_ic;
            out[0] = (float)total;
        }
        __syncthreads();

        /* self-clean for next graph replay */
        for (int i = t; i < 2*BINS; i += 256) g_hist[i] = 0u;
        if (t < NACC) g_acc[t] = 0.0;
        if (t == 0)  g_done = 0u;
    }
}

extern "C" void kernel_launch(void* const* d_in, const int* in_sizes, int n_in,
                              void* d_out, int out_size)
{
    (void)in_sizes; (void)n_in; (void)out_size;
    const float* ypred = (const float*)d_in[0];
    const float* npred = (const float*)d_in[1];
    const float* xi    = (const float*)d_in[2];
    /* d_in[3] = x_ip1 unused by the reference */
    const float* xmid  = (const float*)d_in[4];
    const float* wmap  = (const float*)d_in[5];
    const float* nsyn  = (const float*)d_in[6];

    cudaFuncSetAttribute(k_main, cudaFuncAttributeMaxDynamicSharedMemorySize,
                         SMEM_FLOATS * (int)sizeof(float));
    dim3 grid(GRID_X, GRID_Y, IMG_B);
    k_main<<<grid, 256, SMEM_FLOATS * sizeof(float)>>>(
        ypred, npred, xi, xmid, wmap, nsyn, (float*)d_out);
}